// round 2
// baseline (speedup 1.0000x reference)
#include <cuda_runtime.h>
#include <cuda_bf16.h>
#include <math.h>

#define N      6144
#define F      512
#define H      4
#define FH     64
#define HF     256   // H*FH
#define C      40
#define MAXD   256
#define ALPHA  0.2f

// ---------------- device scratch (no allocations allowed) ----------------
__device__ float g_Wh1[N * HF];        // layer-1 transformed features [N, H*FH]
__device__ float g_f1[H * N];          // per-head source scores
__device__ float g_f2[H * N];          // per-head dest scores
__device__ float g_h[N * HF];          // layer-1 output (ELU'd, concat)
__device__ int   g_nbr[N * MAXD];      // CSR-ish fixed-stride neighbor lists
__device__ int   g_deg[N];
__device__ float g_Wh2[N * C];         // layer-2 transformed features
__device__ float g_f1o[N];
__device__ float g_f2o[N];

// ---------------- kernel A: Wh1 = x @ Wcat  (M=6144,K=512,Ncol=256) ------
#define BM 64
#define BN 64
#define BK 16
__global__ void gemm1_kernel(const float* __restrict__ x,
                             const float* __restrict__ W) {
    __shared__ float As[BK][BM + 1];
    __shared__ float Bs[BK][BN + 1];
    const int tid = threadIdx.x;               // 256 threads
    const int tr = tid / 16, tc = tid % 16;    // 16x16, each 4x4 micro-tile
    const int row0 = blockIdx.y * BM;
    const int col0 = blockIdx.x * BN;

    float acc[4][4];
#pragma unroll
    for (int i = 0; i < 4; i++)
#pragma unroll
        for (int j = 0; j < 4; j++) acc[i][j] = 0.f;

    for (int k0 = 0; k0 < F; k0 += BK) {
        // load A tile 64x16
#pragma unroll
        for (int t = tid; t < BM * BK; t += 256) {
            int m = t / BK, k = t % BK;
            As[k][m] = x[(row0 + m) * F + k0 + k];
        }
        // load B tile 16x64 from W[H][F][FH]
#pragma unroll
        for (int t = tid; t < BK * BN; t += 256) {
            int k = t / BN, j = t % BN;
            int jj = col0 + j;
            int h = jj >> 6, c = jj & 63;
            Bs[k][j] = W[h * (F * FH) + (k0 + k) * FH + c];
        }
        __syncthreads();
#pragma unroll
        for (int k = 0; k < BK; k++) {
            float a[4], b[4];
#pragma unroll
            for (int i = 0; i < 4; i++) a[i] = As[k][tr * 4 + i];
#pragma unroll
            for (int j = 0; j < 4; j++) b[j] = Bs[k][tc * 4 + j];
#pragma unroll
            for (int i = 0; i < 4; i++)
#pragma unroll
                for (int j = 0; j < 4; j++) acc[i][j] += a[i] * b[j];
        }
        __syncthreads();
    }
#pragma unroll
    for (int i = 0; i < 4; i++)
#pragma unroll
        for (int j = 0; j < 4; j++)
            g_Wh1[(row0 + tr * 4 + i) * HF + col0 + tc * 4 + j] = acc[i][j];
}

// ---------------- kernel: per-head attention pre-scores ------------------
__global__ void scores1_kernel(const float* __restrict__ a1,
                               const float* __restrict__ a2) {
    int idx = blockIdx.x * blockDim.x + threadIdx.x;   // N*H
    if (idx >= N * H) return;
    int i = idx >> 2;        // idx / H
    int h = idx & 3;         // idx % H
    const float* wh = &g_Wh1[i * HF + h * FH];
    float s1 = 0.f, s2 = 0.f;
#pragma unroll
    for (int c = 0; c < FH; c++) {
        float v = wh[c];
        s1 += v * a1[h * FH + c];
        s2 += v * a2[h * FH + c];
    }
    g_f1[h * N + i] = s1;
    g_f2[h * N + i] = s2;
}

// ---------------- kernel: adjacency -> neighbor lists (one warp / row) ---
__global__ void build_csr_kernel(const float* __restrict__ adj) {
    int warp = (blockIdx.x * blockDim.x + threadIdx.x) >> 5;
    int lane = threadIdx.x & 31;
    if (warp >= N) return;
    const float* row = adj + (long long)warp * N;
    int cnt = 0;
    for (int j0 = 0; j0 < N; j0 += 32) {
        float v = row[j0 + lane];
        unsigned m = __ballot_sync(0xffffffffu, v > 0.f);
        if (v > 0.f) {
            int pre = __popc(m & ((1u << lane) - 1u));
            int slot = cnt + pre;
            if (slot < MAXD) g_nbr[warp * MAXD + slot] = j0 + lane;
        }
        cnt += __popc(m);
    }
    if (lane == 0) g_deg[warp] = cnt < MAXD ? cnt : MAXD;
}

// ---------------- kernel: layer-1 sparse softmax aggregation + ELU -------
__global__ void agg1_kernel(void) {
    const int i = blockIdx.x;
    const int t = threadIdx.x;          // 256 threads
    const int h = t >> 6, c = t & 63;

    __shared__ int   s_nbr[MAXD];
    __shared__ float s_f2[H][MAXD];

    const int deg = g_deg[i];
    for (int k = t; k < deg; k += 256) s_nbr[k] = g_nbr[i * MAXD + k];
    __syncthreads();
    for (int k = c; k < deg; k += 64) s_f2[h][k] = g_f2[h * N + s_nbr[k]];
    __syncthreads();

    const float f1 = g_f1[h * N + i];
    // pass 1: max (redundant across the 64 threads of a head — cheap)
    float mx = -3.0e38f;
    for (int k = 0; k < deg; k++) {
        float s = f1 + s_f2[h][k];
        s = s > 0.f ? s : ALPHA * s;
        mx = fmaxf(mx, s);
    }
    // pass 2: weighted accumulation
    float sum = 0.f, acc = 0.f;
    for (int k = 0; k < deg; k++) {
        float s = f1 + s_f2[h][k];
        s = s > 0.f ? s : ALPHA * s;
        float w = expf(s - mx);
        sum += w;
        acc += w * g_Wh1[s_nbr[k] * HF + t];   // coalesced 1KB row gather
    }
    float v = acc / sum;
    v = v > 0.f ? v : expm1f(v);               // ELU
    g_h[i * HF + t] = v;
}

// ---------------- kernel: layer-2 GEMM (h @ Wo) --------------------------
__global__ void gemm2_kernel(const float* __restrict__ Wo) {
    int idx = blockIdx.x * blockDim.x + threadIdx.x;   // N*C
    if (idx >= N * C) return;
    int i = idx / C, c = idx % C;
    const float* hr = &g_h[i * HF];
    float s = 0.f;
#pragma unroll 8
    for (int k = 0; k < HF; k++) s += hr[k] * Wo[k * C + c];
    g_Wh2[idx] = s;
}

__global__ void scores2_kernel(const float* __restrict__ ao1,
                               const float* __restrict__ ao2) {
    int i = blockIdx.x * blockDim.x + threadIdx.x;
    if (i >= N) return;
    float s1 = 0.f, s2 = 0.f;
#pragma unroll
    for (int c = 0; c < C; c++) {
        float v = g_Wh2[i * C + c];
        s1 += v * ao1[c];
        s2 += v * ao2[c];
    }
    g_f1o[i] = s1;
    g_f2o[i] = s2;
}

// -------- kernel: layer-2 aggregation + ELU + log_softmax ----------------
__global__ void agg2_kernel(float* __restrict__ out) {
    const int i = blockIdx.x;
    const int t = threadIdx.x;          // 64 threads
    __shared__ int   s_nbr[MAXD];
    __shared__ float s_f2[MAXD];
    __shared__ float red[64];

    const int deg = g_deg[i];
    for (int k = t; k < deg; k += 64) {
        int j = g_nbr[i * MAXD + k];
        s_nbr[k] = j;
        s_f2[k] = g_f2o[j];
    }
    __syncthreads();

    const float f1 = g_f1o[i];
    float mx = -3.0e38f;
    for (int k = 0; k < deg; k++) {
        float s = f1 + s_f2[k];
        s = s > 0.f ? s : ALPHA * s;
        mx = fmaxf(mx, s);
    }
    float sum = 0.f, acc = 0.f;
    for (int k = 0; k < deg; k++) {
        float s = f1 + s_f2[k];
        s = s > 0.f ? s : ALPHA * s;
        float w = expf(s - mx);
        sum += w;
        if (t < C) acc += w * g_Wh2[s_nbr[k] * C + t];
    }
    float v = acc / sum;
    v = v > 0.f ? v : expm1f(v);        // ELU

    // log_softmax over the 40 columns
    red[t] = (t < C) ? v : -3.0e38f;
    __syncthreads();
#pragma unroll
    for (int s = 32; s > 0; s >>= 1) {
        if (t < s) red[t] = fmaxf(red[t], red[t + s]);
        __syncthreads();
    }
    float m2 = red[0];
    __syncthreads();
    red[t] = (t < C) ? expf(v - m2) : 0.f;
    __syncthreads();
#pragma unroll
    for (int s = 32; s > 0; s >>= 1) {
        if (t < s) red[t] += red[t + s];
        __syncthreads();
    }
    float lse = m2 + logf(red[0]);
    if (t < C) out[i * C + t] = v - lse;
}

// ---------------- launch ---------------------------------------------------
extern "C" void kernel_launch(void* const* d_in, const int* in_sizes, int n_in,
                              void* d_out, int out_size) {
    const float* x   = (const float*)d_in[0];   // [N,F]
    const float* adj = (const float*)d_in[1];   // [N,N]
    const float* W   = (const float*)d_in[2];   // [H,F,FH]
    const float* a1  = (const float*)d_in[3];   // [H,FH]
    const float* a2  = (const float*)d_in[4];   // [H,FH]
    const float* Wo  = (const float*)d_in[5];   // [HF,C]
    const float* ao1 = (const float*)d_in[6];   // [C]
    const float* ao2 = (const float*)d_in[7];   // [C]
    float* out = (float*)d_out;                 // [N,C]

    // layer-1 GEMM: [6144,512] @ [512,256]
    dim3 g1(HF / BN, N / BM);
    gemm1_kernel<<<g1, 256>>>(x, W);

    // adjacency scan can overlap nothing here (default stream), but it's
    // independent of gemm1 — keep sequential for round 1.
    build_csr_kernel<<<(N * 32 + 255) / 256, 256>>>(adj);

    scores1_kernel<<<(N * H + 255) / 256, 256>>>(a1, a2);

    agg1_kernel<<<N, 256>>>();

    gemm2_kernel<<<(N * C + 255) / 256, 256>>>(Wo);
    scores2_kernel<<<(N + 255) / 256, 256>>>(ao1, ao2);

    agg2_kernel<<<N, 64>>>(out);
}

// round 3
// speedup vs baseline: 1.1304x; 1.1304x over previous
#include <cuda_runtime.h>
#include <cuda_bf16.h>
#include <math.h>

#define N      6144
#define F      512
#define H      4
#define FH     64
#define HF     256   // H*FH
#define C      40
#define MAXD   256
#define ALPHA  0.2f

// ---------------- device scratch (no allocations allowed) ----------------
__device__ float g_Wh1[N * HF];        // layer-1 transformed features [N, H*FH]
__device__ float g_f1[H * N];          // per-head source scores
__device__ float g_f2[H * N];          // per-head dest scores
__device__ float g_h[N * HF];          // layer-1 output (ELU'd, concat)
__device__ int   g_nbr[N * MAXD];      // fixed-stride neighbor lists
__device__ int   g_deg[N];
__device__ float g_Wh2[N * C];         // layer-2 transformed features
__device__ float g_f1o[N];
__device__ float g_f2o[N];

// ---------------- kernel A: Wh1 = x @ Wcat  (M=6144,K=512,Ncol=256) ------
// 128x64 block tile, 16x16 thread grid, 8x4 micro-tile, float4 loads.
#define BM 128
#define BN 64
#define BK 16
__global__ __launch_bounds__(256) void gemm1_kernel(const float* __restrict__ x,
                                                    const float* __restrict__ W) {
    __shared__ float As[BK][BM + 4];
    __shared__ float Bs[BK][BN + 4];
    const int tid = threadIdx.x;               // 256 threads
    const int tr = tid >> 4, tc = tid & 15;    // 16x16 grid
    const int row0 = blockIdx.y * BM;
    const int col0 = blockIdx.x * BN;          // one head per block col (BN==FH)
    const int h    = col0 >> 6;
    const float* Wh_base = W + h * (F * FH);

    float acc[8][4];
#pragma unroll
    for (int i = 0; i < 8; i++)
#pragma unroll
        for (int j = 0; j < 4; j++) acc[i][j] = 0.f;

    for (int k0 = 0; k0 < F; k0 += BK) {
        // A tile: 128 rows x 16 k  -> 512 float4s, 2 per thread
#pragma unroll
        for (int it = 0; it < 2; it++) {
            int idx = tid + it * 256;
            int m = idx >> 2;                  // 0..127
            int kq = idx & 3;                  // quad along K
            float4 v = *(const float4*)&x[(row0 + m) * F + k0 + kq * 4];
            As[kq * 4 + 0][m] = v.x;
            As[kq * 4 + 1][m] = v.y;
            As[kq * 4 + 2][m] = v.z;
            As[kq * 4 + 3][m] = v.w;
        }
        // B tile: 16 k x 64 cols -> 256 float4s, 1 per thread
        {
            int k = tid >> 4;                  // 0..15
            int cq = tid & 15;                 // 0..15
            float4 v = *(const float4*)&Wh_base[(k0 + k) * FH + cq * 4];
            Bs[k][cq * 4 + 0] = v.x;
            Bs[k][cq * 4 + 1] = v.y;
            Bs[k][cq * 4 + 2] = v.z;
            Bs[k][cq * 4 + 3] = v.w;
        }
        __syncthreads();
#pragma unroll
        for (int k = 0; k < BK; k++) {
            float4 a0 = *(const float4*)&As[k][tr * 8];
            float4 a1 = *(const float4*)&As[k][tr * 8 + 4];
            float4 bv = *(const float4*)&Bs[k][tc * 4];
            float a[8] = {a0.x, a0.y, a0.z, a0.w, a1.x, a1.y, a1.z, a1.w};
            float b[4] = {bv.x, bv.y, bv.z, bv.w};
#pragma unroll
            for (int i = 0; i < 8; i++)
#pragma unroll
                for (int j = 0; j < 4; j++) acc[i][j] += a[i] * b[j];
        }
        __syncthreads();
    }
#pragma unroll
    for (int i = 0; i < 8; i++) {
        float4 v = {acc[i][0], acc[i][1], acc[i][2], acc[i][3]};
        *(float4*)&g_Wh1[(row0 + tr * 8 + i) * HF + col0 + tc * 4] = v;
    }
}

// ---------------- kernel: per-head attention pre-scores ------------------
__global__ void scores1_kernel(const float* __restrict__ a1,
                               const float* __restrict__ a2) {
    int idx = blockIdx.x * blockDim.x + threadIdx.x;   // N*H
    if (idx >= N * H) return;
    int i = idx >> 2;
    int h = idx & 3;
    const float* wh = &g_Wh1[i * HF + h * FH];
    float s1 = 0.f, s2 = 0.f;
#pragma unroll
    for (int c = 0; c < FH; c++) {
        float v = wh[c];
        s1 += v * a1[h * FH + c];
        s2 += v * a2[h * FH + c];
    }
    g_f1[h * N + i] = s1;
    g_f2[h * N + i] = s2;
}

// ---------------- kernel: adjacency -> neighbor lists (one warp / row) ---
__global__ void build_csr_kernel(const float* __restrict__ adj) {
    int warp = (blockIdx.x * blockDim.x + threadIdx.x) >> 5;
    int lane = threadIdx.x & 31;
    if (warp >= N) return;
    const float* row = adj + (long long)warp * N;
    int cnt = 0;
    for (int j0 = 0; j0 < N; j0 += 32) {
        float v = row[j0 + lane];
        unsigned m = __ballot_sync(0xffffffffu, v > 0.f);
        if (v > 0.f) {
            int pre = __popc(m & ((1u << lane) - 1u));
            int slot = cnt + pre;
            if (slot < MAXD) g_nbr[warp * MAXD + slot] = j0 + lane;
        }
        cnt += __popc(m);
    }
    if (lane == 0) g_deg[warp] = cnt < MAXD ? cnt : MAXD;
}

// ---------------- kernel: layer-1 sparse softmax aggregation + ELU -------
// 256 threads = 4 heads x 64 lanes. Softmax weights computed cooperatively
// once per head (strided over deg), cached in smem; gather loop is pure FMA.
__global__ __launch_bounds__(256) void agg1_kernel(void) {
    const int i = blockIdx.x;
    const int t = threadIdx.x;
    const int h = t >> 6, c = t & 63;
    const int lane = t & 31;
    const int half = (t >> 5) & 1;      // which of the head's two warps

    __shared__ int   s_nbr[MAXD];
    __shared__ float s_w[H][MAXD];
    __shared__ float s_red[H][2];
    __shared__ float s_sum[H][2];

    const int deg = g_deg[i];
    for (int k = t; k < deg; k += 256) s_nbr[k] = g_nbr[i * MAXD + k];
    __syncthreads();

    const float f1 = g_f1[h * N + i];

    // phase 1: scores (leaky-relu'd) strided across 64 lanes; store raw s
    float lmax = -3.0e38f;
    for (int k = c; k < deg; k += 64) {
        float s = f1 + g_f2[h * N + s_nbr[k]];
        s = s > 0.f ? s : ALPHA * s;
        s_w[h][k] = s;
        lmax = fmaxf(lmax, s);
    }
#pragma unroll
    for (int o = 16; o > 0; o >>= 1)
        lmax = fmaxf(lmax, __shfl_xor_sync(0xffffffffu, lmax, o));
    if (lane == 0) s_red[h][half] = lmax;
    __syncthreads();
    const float mx = fmaxf(s_red[h][0], s_red[h][1]);

    // phase 2: w = exp(s - mx); partial sum
    float lsum = 0.f;
    for (int k = c; k < deg; k += 64) {
        float w = expf(s_w[h][k] - mx);
        s_w[h][k] = w;
        lsum += w;
    }
#pragma unroll
    for (int o = 16; o > 0; o >>= 1)
        lsum += __shfl_xor_sync(0xffffffffu, lsum, o);
    if (lane == 0) s_sum[h][half] = lsum;
    __syncthreads();
    const float sum = s_sum[h][0] + s_sum[h][1];

    // phase 3: weighted gather (coalesced 1KB row reads from L2)
    float acc = 0.f;
    for (int k = 0; k < deg; k++)
        acc += s_w[h][k] * g_Wh1[s_nbr[k] * HF + t];

    float v = acc / sum;
    v = v > 0.f ? v : expm1f(v);               // ELU
    g_h[i * HF + t] = v;
}

// ---------------- kernel: layer-2 GEMM (h @ Wo) --------------------------
__global__ void gemm2_kernel(const float* __restrict__ Wo) {
    int idx = blockIdx.x * blockDim.x + threadIdx.x;   // N*C
    if (idx >= N * C) return;
    int i = idx / C, c = idx % C;
    const float* hr = &g_h[i * HF];
    float s = 0.f;
#pragma unroll 8
    for (int k = 0; k < HF; k++) s += hr[k] * Wo[k * C + c];
    g_Wh2[idx] = s;
}

__global__ void scores2_kernel(const float* __restrict__ ao1,
                               const float* __restrict__ ao2) {
    int i = blockIdx.x * blockDim.x + threadIdx.x;
    if (i >= N) return;
    float s1 = 0.f, s2 = 0.f;
#pragma unroll
    for (int c = 0; c < C; c++) {
        float v = g_Wh2[i * C + c];
        s1 += v * ao1[c];
        s2 += v * ao2[c];
    }
    g_f1o[i] = s1;
    g_f2o[i] = s2;
}

// -------- kernel: layer-2 aggregation + ELU + log_softmax ----------------
__global__ void agg2_kernel(float* __restrict__ out) {
    const int i = blockIdx.x;
    const int t = threadIdx.x;          // 64 threads
    __shared__ int   s_nbr[MAXD];
    __shared__ float s_f2[MAXD];
    __shared__ float red[64];

    const int deg = g_deg[i];
    for (int k = t; k < deg; k += 64) {
        int j = g_nbr[i * MAXD + k];
        s_nbr[k] = j;
        s_f2[k] = g_f2o[j];
    }
    __syncthreads();

    const float f1 = g_f1o[i];
    float mx = -3.0e38f;
    for (int k = 0; k < deg; k++) {
        float s = f1 + s_f2[k];
        s = s > 0.f ? s : ALPHA * s;
        mx = fmaxf(mx, s);
    }
    float sum = 0.f, acc = 0.f;
    for (int k = 0; k < deg; k++) {
        float s = f1 + s_f2[k];
        s = s > 0.f ? s : ALPHA * s;
        float w = expf(s - mx);
        sum += w;
        if (t < C) acc += w * g_Wh2[s_nbr[k] * C + t];
    }
    float v = acc / sum;
    v = v > 0.f ? v : expm1f(v);        // ELU

    // log_softmax over the 40 columns
    red[t] = (t < C) ? v : -3.0e38f;
    __syncthreads();
#pragma unroll
    for (int s = 32; s > 0; s >>= 1) {
        if (t < s) red[t] = fmaxf(red[t], red[t + s]);
        __syncthreads();
    }
    float m2 = red[0];
    __syncthreads();
    red[t] = (t < C) ? expf(v - m2) : 0.f;
    __syncthreads();
#pragma unroll
    for (int s = 32; s > 0; s >>= 1) {
        if (t < s) red[t] += red[t + s];
        __syncthreads();
    }
    float lse = m2 + logf(red[0]);
    if (t < C) out[i * C + t] = v - lse;
}

// ---------------- launch ---------------------------------------------------
extern "C" void kernel_launch(void* const* d_in, const int* in_sizes, int n_in,
                              void* d_out, int out_size) {
    const float* x   = (const float*)d_in[0];   // [N,F]
    const float* adj = (const float*)d_in[1];   // [N,N]
    const float* W   = (const float*)d_in[2];   // [H,F,FH]
    const float* a1  = (const float*)d_in[3];   // [H,FH]
    const float* a2  = (const float*)d_in[4];   // [H,FH]
    const float* Wo  = (const float*)d_in[5];   // [HF,C]
    const float* ao1 = (const float*)d_in[6];   // [C]
    const float* ao2 = (const float*)d_in[7];   // [C]
    float* out = (float*)d_out;                 // [N,C]

    // side stream + events for capture-legal fork/join (created once, before
    // any capture happens — first call is the correctness run)
    static cudaStream_t s2 = nullptr;
    static cudaEvent_t ev_fork = nullptr, ev_join = nullptr;
    if (!s2) {
        cudaStreamCreateWithFlags(&s2, cudaStreamNonBlocking);
        cudaEventCreateWithFlags(&ev_fork, cudaEventDisableTiming);
        cudaEventCreateWithFlags(&ev_join, cudaEventDisableTiming);
    }

    // fork: build_csr (pure DRAM) overlaps gemm1 (pure compute)
    cudaEventRecord(ev_fork, 0);
    cudaStreamWaitEvent(s2, ev_fork, 0);
    build_csr_kernel<<<(N * 32 + 255) / 256, 256, 0, s2>>>(adj);
    cudaEventRecord(ev_join, s2);

    // layer-1 GEMM: [6144,512] @ [512,256]
    dim3 g1(HF / BN, N / BM);
    gemm1_kernel<<<g1, 256>>>(x, W);
    scores1_kernel<<<(N * H + 255) / 256, 256>>>(a1, a2);

    // join before aggregation needs the CSR
    cudaStreamWaitEvent(0, ev_join, 0);
    agg1_kernel<<<N, 256>>>();

    gemm2_kernel<<<(N * C + 255) / 256, 256>>>(Wo);
    scores2_kernel<<<(N + 255) / 256, 256>>>(ao1, ao2);

    agg2_kernel<<<N, 64>>>(out);
}

// round 7
// speedup vs baseline: 1.4114x; 1.2486x over previous
#include <cuda_runtime.h>
#include <cuda_bf16.h>
#include <math.h>

#define N      6144
#define F      512
#define H      4
#define FH     64
#define HF     256   // H*FH
#define C      40
#define MAXD   256
#define ALPHA  0.2f

// ---------------- device scratch ----------------
__device__ float g_Wh1[N * HF];
__device__ float g_f1[H * N];
__device__ float g_f2[H * N];
__device__ float g_h[N * HF];
__device__ int   g_nbr[N * MAXD];
__device__ int   g_deg[N];
__device__ float g_Wh2[N * C];
__device__ float g_f1o[N];
__device__ float g_f2o[N];

// ================= gemm1: Wh1 = x @ Wcat via 3xTF32 tensor-core MMA ======
// M=6144, Ncols=256 (4 heads x 64), K=512.
// Block tile 128x64, 8 warps in 4(M) x 2(N), warp tile 32x32.
// Each fp32 operand split into tf32 hi + tf32 lo; D += Ahi*Bhi + Alo*Bhi + Ahi*Blo.
#define GBM 128
#define GBN 64
#define GBK 32
#define SPAD 36   // smem row pad: bank-conflict-free fragment loads

__device__ __forceinline__ void split_tf32(float v, unsigned& hi, unsigned& lo) {
    asm("cvt.rna.tf32.f32 %0, %1;" : "=r"(hi) : "f"(v));
    float r = v - __uint_as_float(hi);
    asm("cvt.rna.tf32.f32 %0, %1;" : "=r"(lo) : "f"(r));
}

#define MMA_TF32(d, a, b)                                                     \
    asm volatile(                                                             \
        "mma.sync.aligned.m16n8k8.row.col.f32.tf32.tf32.f32 "                 \
        "{%0,%1,%2,%3}, {%4,%5,%6,%7}, {%8,%9}, {%0,%1,%2,%3};"               \
        : "+f"(d[0]), "+f"(d[1]), "+f"(d[2]), "+f"(d[3])                      \
        : "r"(a[0]), "r"(a[1]), "r"(a[2]), "r"(a[3]), "r"(b[0]), "r"(b[1]))

__global__ __launch_bounds__(256) void gemm1_tc(const float* __restrict__ x,
                                                const float* __restrict__ W) {
    __shared__ float As[GBM][SPAD];   // [row][k]
    __shared__ float Bs[GBN][SPAD];   // [n][k]
    const int tid = threadIdx.x;
    const int wid = tid >> 5, lane = tid & 31;
    const int group = lane >> 2, tig = lane & 3;
    const int warp_m = wid >> 1, warp_n = wid & 1;
    const int row0 = blockIdx.y * GBM;
    const int col0 = blockIdx.x * GBN;           // one head per block col
    const float* Wb = W + (col0 >> 6) * (F * FH);

    float acc[2][4][4];
#pragma unroll
    for (int mt = 0; mt < 2; mt++)
#pragma unroll
        for (int nt = 0; nt < 4; nt++)
#pragma unroll
            for (int j = 0; j < 4; j++) acc[mt][nt][j] = 0.f;

    for (int k0 = 0; k0 < F; k0 += GBK) {
        // A tile: 128 rows x 32 k = 1024 float4
#pragma unroll
        for (int it = 0; it < 4; it++) {
            int idx = tid + it * 256;
            int m = idx >> 3, q = idx & 7;
            float4 v = *(const float4*)&x[(row0 + m) * F + k0 + q * 4];
            As[m][q * 4 + 0] = v.x;
            As[m][q * 4 + 1] = v.y;
            As[m][q * 4 + 2] = v.z;
            As[m][q * 4 + 3] = v.w;
        }
        // B tile: 32 k x 64 c = 512 float4, stored transposed [n][k]
#pragma unroll
        for (int it = 0; it < 2; it++) {
            int idx = tid + it * 256;
            int k = idx >> 4, cq = idx & 15;
            float4 v = *(const float4*)&Wb[(k0 + k) * FH + cq * 4];
            Bs[cq * 4 + 0][k] = v.x;
            Bs[cq * 4 + 1][k] = v.y;
            Bs[cq * 4 + 2][k] = v.z;
            Bs[cq * 4 + 3][k] = v.w;
        }
        __syncthreads();
#pragma unroll
        for (int kk = 0; kk < 4; kk++) {
            const int kb = kk * 8;
            unsigned ahi[2][4], alo[2][4];
#pragma unroll
            for (int mt = 0; mt < 2; mt++) {
                int rb = warp_m * 32 + mt * 16;
                float a0 = As[rb + group][kb + tig];
                float a1 = As[rb + group + 8][kb + tig];
                float a2 = As[rb + group][kb + tig + 4];
                float a3 = As[rb + group + 8][kb + tig + 4];
                split_tf32(a0, ahi[mt][0], alo[mt][0]);
                split_tf32(a1, ahi[mt][1], alo[mt][1]);
                split_tf32(a2, ahi[mt][2], alo[mt][2]);
                split_tf32(a3, ahi[mt][3], alo[mt][3]);
            }
            unsigned bhi[4][2], blo[4][2];
#pragma unroll
            for (int nt = 0; nt < 4; nt++) {
                int n = warp_n * 32 + nt * 8 + group;
                float b0 = Bs[n][kb + tig];
                float b1 = Bs[n][kb + tig + 4];
                split_tf32(b0, bhi[nt][0], blo[nt][0]);
                split_tf32(b1, bhi[nt][1], blo[nt][1]);
            }
#pragma unroll
            for (int mt = 0; mt < 2; mt++)
#pragma unroll
                for (int nt = 0; nt < 4; nt++) {
                    MMA_TF32(acc[mt][nt], ahi[mt], bhi[nt]);
                    MMA_TF32(acc[mt][nt], alo[mt], bhi[nt]);
                    MMA_TF32(acc[mt][nt], ahi[mt], blo[nt]);
                }
        }
        __syncthreads();
    }
    // epilogue
#pragma unroll
    for (int mt = 0; mt < 2; mt++)
#pragma unroll
        for (int nt = 0; nt < 4; nt++) {
            int r = row0 + warp_m * 32 + mt * 16 + group;
            int cc = col0 + warp_n * 32 + nt * 8 + tig * 2;
            float2 v0 = {acc[mt][nt][0], acc[mt][nt][1]};
            float2 v1 = {acc[mt][nt][2], acc[mt][nt][3]};
            *(float2*)&g_Wh1[r * HF + cc] = v0;
            *(float2*)&g_Wh1[(r + 8) * HF + cc] = v1;
        }
}

// ---------------- scores1 ------------------------------------------------
__global__ void scores1_kernel(const float* __restrict__ a1,
                               const float* __restrict__ a2) {
    int idx = blockIdx.x * blockDim.x + threadIdx.x;
    if (idx >= N * H) return;
    int i = idx >> 2;
    int h = idx & 3;
    const float* wh = &g_Wh1[i * HF + h * FH];
    float s1 = 0.f, s2 = 0.f;
#pragma unroll
    for (int c = 0; c < FH; c++) {
        float v = wh[c];
        s1 += v * a1[h * FH + c];
        s2 += v * a2[h * FH + c];
    }
    g_f1[h * N + i] = s1;
    g_f2[h * N + i] = s2;
}

// ---------------- build CSR ----------------------------------------------
__global__ void build_csr_kernel(const float* __restrict__ adj) {
    int warp = (blockIdx.x * blockDim.x + threadIdx.x) >> 5;
    int lane = threadIdx.x & 31;
    if (warp >= N) return;
    const float* row = adj + (long long)warp * N;
    int cnt = 0;
    for (int j0 = 0; j0 < N; j0 += 32) {
        float v = row[j0 + lane];
        unsigned m = __ballot_sync(0xffffffffu, v > 0.f);
        if (v > 0.f) {
            int pre = __popc(m & ((1u << lane) - 1u));
            int slot = cnt + pre;
            if (slot < MAXD) g_nbr[warp * MAXD + slot] = j0 + lane;
        }
        cnt += __popc(m);
    }
    if (lane == 0) g_deg[warp] = cnt < MAXD ? cnt : MAXD;
}

// ---------------- agg1: layer-1 softmax aggregation + ELU ----------------
__global__ __launch_bounds__(256) void agg1_kernel(void) {
    const int i = blockIdx.x;
    const int t = threadIdx.x;
    const int h = t >> 6, c = t & 63;
    const int lane = t & 31;
    const int half = (t >> 5) & 1;

    __shared__ int   s_nbr[MAXD];
    __shared__ float s_w[H][MAXD];
    __shared__ float s_red[H][2];
    __shared__ float s_sum[H][2];

    const int deg = g_deg[i];
    for (int k = t; k < deg; k += 256) s_nbr[k] = g_nbr[i * MAXD + k];
    __syncthreads();

    const float f1 = g_f1[h * N + i];

    float lmax = -3.0e38f;
    for (int k = c; k < deg; k += 64) {
        float s = f1 + g_f2[h * N + s_nbr[k]];
        s = s > 0.f ? s : ALPHA * s;
        s_w[h][k] = s;
        lmax = fmaxf(lmax, s);
    }
#pragma unroll
    for (int o = 16; o > 0; o >>= 1)
        lmax = fmaxf(lmax, __shfl_xor_sync(0xffffffffu, lmax, o));
    if (lane == 0) s_red[h][half] = lmax;
    __syncthreads();
    const float mx = fmaxf(s_red[h][0], s_red[h][1]);

    float lsum = 0.f;
    for (int k = c; k < deg; k += 64) {
        float w = expf(s_w[h][k] - mx);
        s_w[h][k] = w;
        lsum += w;
    }
#pragma unroll
    for (int o = 16; o > 0; o >>= 1)
        lsum += __shfl_xor_sync(0xffffffffu, lsum, o);
    if (lane == 0) s_sum[h][half] = lsum;
    __syncthreads();
    const float sum = s_sum[h][0] + s_sum[h][1];

    // weighted gather, unrolled x4 for MLP
    float acc = 0.f;
    int k = 0;
    for (; k + 4 <= deg; k += 4) {
        float w0 = s_w[h][k], w1 = s_w[h][k + 1], w2 = s_w[h][k + 2], w3 = s_w[h][k + 3];
        const float* r0 = &g_Wh1[s_nbr[k] * HF];
        const float* r1 = &g_Wh1[s_nbr[k + 1] * HF];
        const float* r2 = &g_Wh1[s_nbr[k + 2] * HF];
        const float* r3 = &g_Wh1[s_nbr[k + 3] * HF];
        float v0 = __ldg(r0 + t), v1 = __ldg(r1 + t), v2 = __ldg(r2 + t), v3 = __ldg(r3 + t);
        acc += w0 * v0 + w1 * v1 + w2 * v2 + w3 * v3;
    }
    for (; k < deg; k++)
        acc += s_w[h][k] * g_Wh1[s_nbr[k] * HF + t];

    float v = acc / sum;
    v = v > 0.f ? v : expm1f(v);
    g_h[i * HF + t] = v;
}

// ---------------- gemm2: Wh2 = h @ Wo, smem-staged, register-tiled -------
#define G2R 32
__global__ __launch_bounds__(256) void gemm2_kernel(const float* __restrict__ Wo) {
    __shared__ float sh[G2R][HF + 4];   // [row][k], float4 stores, conflict-free
    const int i0 = blockIdx.x * G2R;
    const int tid = threadIdx.x;

#pragma unroll
    for (int it = 0; it < 8; it++) {
        int idx = tid + it * 256;
        int r = idx >> 6, kq = idx & 63;
        float4 v = *(const float4*)&g_h[(i0 + r) * HF + kq * 4];
        *(float4*)&sh[r][kq * 4] = v;
    }
    __syncthreads();

    if (tid < 160) {
        int c = tid % 40;
        int rg = tid / 40;              // 0..3, 8 rows each
        float acc[8];
#pragma unroll
        for (int j = 0; j < 8; j++) acc[j] = 0.f;
        for (int k = 0; k < HF; k++) {
            float wv = __ldg(&Wo[k * C + c]);
#pragma unroll
            for (int j = 0; j < 8; j++)
                acc[j] += wv * sh[rg * 8 + j][k];
        }
#pragma unroll
        for (int j = 0; j < 8; j++)
            g_Wh2[(i0 + rg * 8 + j) * C + c] = acc[j];
    }
}

__global__ void scores2_kernel(const float* __restrict__ ao1,
                               const float* __restrict__ ao2) {
    int i = blockIdx.x * blockDim.x + threadIdx.x;
    if (i >= N) return;
    float s1 = 0.f, s2 = 0.f;
#pragma unroll
    for (int c = 0; c < C; c++) {
        float v = g_Wh2[i * C + c];
        s1 += v * ao1[c];
        s2 += v * ao2[c];
    }
    g_f1o[i] = s1;
    g_f2o[i] = s2;
}

// -------- agg2: layer-2 aggregation + ELU + log_softmax ------------------
__global__ __launch_bounds__(64) void agg2_kernel(float* __restrict__ out) {
    const int i = blockIdx.x;
    const int t = threadIdx.x;          // 64 threads, 2 warps
    const int lane = t & 31, w = t >> 5;
    __shared__ int   s_nbr[MAXD];
    __shared__ float s_w[MAXD];
    __shared__ float s_r[2];
    __shared__ float red[64];

    const int deg = g_deg[i];
    const float f1 = g_f1o[i];

    float lmax = -3.0e38f;
    for (int k = t; k < deg; k += 64) {
        int j = g_nbr[i * MAXD + k];
        s_nbr[k] = j;
        float s = f1 + g_f2o[j];
        s = s > 0.f ? s : ALPHA * s;
        s_w[k] = s;
        lmax = fmaxf(lmax, s);
    }
#pragma unroll
    for (int o = 16; o > 0; o >>= 1)
        lmax = fmaxf(lmax, __shfl_xor_sync(0xffffffffu, lmax, o));
    if (lane == 0) s_r[w] = lmax;
    __syncthreads();
    const float mx = fmaxf(s_r[0], s_r[1]);

    float lsum = 0.f;
    for (int k = t; k < deg; k += 64) {
        float e = expf(s_w[k] - mx);
        s_w[k] = e;
        lsum += e;
    }
#pragma unroll
    for (int o = 16; o > 0; o >>= 1)
        lsum += __shfl_xor_sync(0xffffffffu, lsum, o);
    __syncthreads();                    // mx reads + s_w writes settle
    if (lane == 0) s_r[w] = lsum;
    __syncthreads();
    const float sum = s_r[0] + s_r[1];

    float acc = 0.f;
    if (t < C) {
        for (int k = 0; k < deg; k++)
            acc += s_w[k] * g_Wh2[s_nbr[k] * C + t];
    }
    float v = acc / sum;
    v = v > 0.f ? v : expm1f(v);        // ELU

    // log_softmax over 40 columns
    red[t] = (t < C) ? v : -3.0e38f;
    __syncthreads();
#pragma unroll
    for (int s = 32; s > 0; s >>= 1) {
        if (t < s) red[t] = fmaxf(red[t], red[t + s]);
        __syncthreads();
    }
    float m2 = red[0];
    __syncthreads();
    red[t] = (t < C) ? expf(v - m2) : 0.f;
    __syncthreads();
#pragma unroll
    for (int s = 32; s > 0; s >>= 1) {
        if (t < s) red[t] += red[t + s];
        __syncthreads();
    }
    float lse = m2 + logf(red[0]);
    if (t < C) out[i * C + t] = v - lse;
}

// ---------------- launch ---------------------------------------------------
extern "C" void kernel_launch(void* const* d_in, const int* in_sizes, int n_in,
                              void* d_out, int out_size) {
    const float* x   = (const float*)d_in[0];
    const float* adj = (const float*)d_in[1];
    const float* W   = (const float*)d_in[2];
    const float* a1  = (const float*)d_in[3];
    const float* a2  = (const float*)d_in[4];
    const float* Wo  = (const float*)d_in[5];
    const float* ao1 = (const float*)d_in[6];
    const float* ao2 = (const float*)d_in[7];
    float* out = (float*)d_out;

    static cudaStream_t s2 = nullptr;
    static cudaEvent_t ev_fork = nullptr, ev_join = nullptr;
    if (!s2) {
        cudaStreamCreateWithFlags(&s2, cudaStreamNonBlocking);
        cudaEventCreateWithFlags(&ev_fork, cudaEventDisableTiming);
        cudaEventCreateWithFlags(&ev_join, cudaEventDisableTiming);
    }

    // fork: build_csr (pure DRAM) overlaps gemm1 (pure tensor compute)
    cudaEventRecord(ev_fork, 0);
    cudaStreamWaitEvent(s2, ev_fork, 0);
    build_csr_kernel<<<(N * 32 + 255) / 256, 256, 0, s2>>>(adj);
    cudaEventRecord(ev_join, s2);

    dim3 g1(HF / GBN, N / GBM);         // (4, 48)
    gemm1_tc<<<g1, 256>>>(x, W);
    scores1_kernel<<<(N * H + 255) / 256, 256>>>(a1, a2);

    cudaStreamWaitEvent(0, ev_join, 0);
    agg1_kernel<<<N, 256>>>();

    gemm2_kernel<<<N / G2R, 256>>>(Wo);
    scores2_kernel<<<(N + 255) / 256, 256>>>(ao1, ao2);

    agg2_kernel<<<N, 64>>>(out);
}